// round 17
// baseline (speedup 1.0000x reference)
#include <cuda_runtime.h>
#include <cuda_bf16.h>
#include <math.h>

#define NN 8192
#define DD 512

// Scratch (static device globals — no runtime allocation allowed)
__device__ float g_featn[(size_t)NN * DD];                     // normalized feats
__device__ __align__(16) __nv_bfloat16 g_sp0[(size_t)NN * DD]; // bf16 of featn
__device__ float g_pos[(size_t)NN * 2];
__device__ float g_lam, g_one_m_lam, g_temp;        // exp-form (output values)
__device__ float g_lam_key, g_oml_key;              // XLA tanh-form (ranking keys)

// m16n8k16 bf16 MMA, fp32 accumulate (plain PTX, valid on sm_103)
#define MMA16816(d, a, b0v, b1v)                                              \
    asm volatile(                                                             \
        "mma.sync.aligned.m16n8k16.row.col.f32.bf16.bf16.f32 "                \
        "{%0,%1,%2,%3}, {%4,%5,%6,%7}, {%8,%9}, {%0,%1,%2,%3};"               \
        : "+f"((d)[0]), "+f"((d)[1]), "+f"((d)[2]), "+f"((d)[3])              \
        : "r"((a)[0]), "r"((a)[1]), "r"((a)[2]), "r"((a)[3]),                 \
          "r"(b0v), "r"(b1v))

#define LDSM_X4(r, addr)                                                      \
    asm volatile("ldmatrix.sync.aligned.m8n8.x4.shared.b16 {%0,%1,%2,%3}, [%4];" \
        : "=r"((r)[0]), "=r"((r)[1]), "=r"((r)[2]), "=r"((r)[3]) : "r"(addr))

#define CP_ASYNC16(dst, src)                                                  \
    asm volatile("cp.async.ca.shared.global [%0], [%1], 16;" :: "r"(dst), "l"(src))
#define CP_COMMIT() asm volatile("cp.async.commit_group;" ::: "memory")
#define CP_WAIT0()  asm volatile("cp.async.wait_group 0;" ::: "memory")

__device__ __forceinline__ unsigned int smem_u32(const void* p) {
    return (unsigned int)__cvta_generic_to_shared(p);
}

// ---------------------------------------------------------------------------
// Numerics helpers (validated rounds 1-6 — DO NOT CHANGE)
// ---------------------------------------------------------------------------
__device__ __forceinline__ float sigmoid_f(float x) {
    if (x >= 0.0f) {
        float e = expf(-x);
        return __fdiv_rn(1.0f, __fadd_rn(1.0f, e));
    } else {
        float e = expf(x);
        return __fdiv_rn(e, __fadd_rn(1.0f, e));
    }
}

__device__ __forceinline__ float xla_tanh_f32(float x) {
    const float kClamp = 7.90531110763549805f;
    float xc = fminf(fmaxf(x, -kClamp), kClamp);
    float x2 = __fmul_rn(xc, xc);
    float p = __fmaf_rn(x2, -2.76076847742355e-16f, 2.00018790482477e-13f);
    p = __fmaf_rn(x2, p, -8.60467152213735e-11f);
    p = __fmaf_rn(x2, p, 5.12229709037114e-08f);
    p = __fmaf_rn(x2, p, 1.48572235717979e-05f);
    p = __fmaf_rn(x2, p, 6.37261928875436e-04f);
    p = __fmaf_rn(x2, p, 4.89352455891786e-03f);
    float num = __fmul_rn(xc, p);
    float q = __fmaf_rn(x2, 1.19825839466702e-06f, 1.18534705686654e-04f);
    q = __fmaf_rn(x2, q, 2.26843463243900e-03f);
    q = __fmaf_rn(x2, q, 4.89352518554385e-03f);
    float r = __fdiv_rn(num, q);
    return (fabsf(x) < 0.0004f) ? x : r;
}

__device__ __forceinline__ float xla_logistic_f32(float x) {
    float t = xla_tanh_f32(__fmul_rn(0.5f, x));
    return __fadd_rn(0.5f, __fmul_rn(0.5f, t));
}

__device__ __forceinline__ float ref_adj_key(float simf, int i, int j,
                                             float lamk, float omlk, float temp) {
    float px = g_pos[2 * i], py = g_pos[2 * i + 1];
    float qx = g_pos[2 * j], qy = g_pos[2 * j + 1];
    float sqa = __fadd_rn(__fmul_rn(px, px), __fmul_rn(py, py));
    float sqb = __fadd_rn(__fmul_rn(qx, qx), __fmul_rn(qy, qy));
    float P = __fmaf_rn(py, qy, __fmul_rn(px, qx));
    float S = __fadd_rn(sqa, sqb);
    float d2 = __fadd_rn(S, -(2.0f * P));
    d2 = fmaxf(d2, 0.0f);
    float arg = -__fdiv_rn(d2, 5000.0f);
    float sp = (float)exp((double)arg);     // correctly-rounded fp32 exp
    float comb = __fadd_rn(__fmul_rn(lamk, simf), __fmul_rn(omlk, sp));
    float z = __fmul_rn(comb, temp);
    return xla_logistic_f32(z);
}

// ---------------------------------------------------------------------------
// Kernel 1: row-normalize (fp64 norm) + bf16 quantization of normalized feats.
// ---------------------------------------------------------------------------
__global__ void prep_kernel(const float* __restrict__ feat,
                            const float* __restrict__ pos,
                            const float* __restrict__ lamw,
                            const float* __restrict__ temp) {
    int gwarp = (blockIdx.x * blockDim.x + threadIdx.x) >> 5;
    int lane = threadIdx.x & 31;
    if (gwarp >= NN) return;
    const float* src = feat + (size_t)gwarp * DD;

    double ss = 0.0;
#pragma unroll
    for (int j = lane; j < DD; j += 32) {
        double v = (double)src[j];
        ss += v * v;
    }
#pragma unroll
    for (int off = 16; off > 0; off >>= 1)
        ss += __shfl_down_sync(0xFFFFFFFFu, ss, off);
    ss = __shfl_sync(0xFFFFFFFFu, ss, 0);

    float nrm = fmaxf((float)sqrt(ss), 1e-12f);
    size_t base = (size_t)gwarp * DD;
#pragma unroll
    for (int j = lane; j < DD; j += 32) {
        float v = __fdiv_rn(src[j], nrm);
        g_featn[base + j] = v;
        g_sp0[base + j] = __float2bfloat16_rn(v);
    }

    if (lane < 2) g_pos[2 * gwarp + lane] = pos[2 * gwarp + lane];
    if (gwarp == 0 && lane == 0) {
        float lam = sigmoid_f(*lamw);
        g_lam = lam;
        g_one_m_lam = 1.0f - lam;
        g_temp = *temp;
        float lamk = xla_logistic_f32(*lamw);   // reference's lam
        g_lam_key = lamk;
        g_oml_key = __fadd_rn(1.0f, -lamk);
    }
}

// ---------------------------------------------------------------------------
// Kernel 2: mma.sync bf16 single-product GEMM. 256 threads, 2 CTAs/SM
// (cross-CTA overlap of staging/epilogue with MMA). Per-accumulator K order
// identical to round 14/15 -> bitwise identical sim.
// ---------------------------------------------------------------------------
#define NTILE (NN / 128)                   // 64
#define NPAIRS (NTILE * (NTILE + 1) / 2)   // 2080
#define STAGE 32768                        // one buffer: A0 16 KB + B0 16 KB
#define DYN_SMEM 66048                     // max(2*STAGE, 128*129*4)
#define GT 256                             // GEMM threads

// stage one 64-col k-chunk into buffer `base` (swizzled, coalesced)
__device__ __forceinline__ void stage_chunk(unsigned int base, int m0, int n0,
                                            int k0, int tid) {
#pragma unroll
    for (int it = 0; it < 8; it++) {
        int u = it * GT + tid;         // 0..2047
        int mat = u >> 10;             // 0:A0 1:B0
        int idx = u & 1023;
        int row = idx >> 3;
        int grp = idx & 7;
        int grow = ((mat == 0) ? m0 : n0) + row;
        const void* src = (const void*)(g_sp0 + (size_t)grow * DD + k0 + grp * 8);
        unsigned int dst = base + (unsigned)(mat * 16384 + row * 128 +
                                             ((grp ^ (row & 7)) << 4));
        CP_ASYNC16(dst, src);
    }
}

__global__ __launch_bounds__(GT, 2)
void adj_gemm_mma(const float* __restrict__ pos, float* __restrict__ outp) {
    extern __shared__ char dyn[];
    __shared__ float s_qx[128], s_qy[128], s_sqb[128];

    // decode linear tile id -> (bi, bj), bj >= bi
    int t = blockIdx.x;
    int bi = (int)((2.0 * NTILE + 1.0 -
                    sqrt((2.0 * NTILE + 1.0) * (2.0 * NTILE + 1.0) - 8.0 * (double)t)) * 0.5);
    while ((bi + 1) * NTILE - ((bi + 1) * bi) / 2 <= t) bi++;
    while (bi * NTILE - (bi * (bi - 1)) / 2 > t) bi--;
    int bj = bi + (t - (bi * NTILE - (bi * (bi - 1)) / 2));

    const int m0 = bi * 128, n0 = bj * 128;
    const int tid = threadIdx.x;
    const int wid = tid >> 5;
    const int lane = tid & 31;
    const int gid = lane >> 2;
    const int tig = lane & 3;
    const int lane7 = lane & 7;

    const int wm = (wid >> 2) * 64;   // warp m-offset (0 or 64)
    const int wn = (wid & 3) * 32;    // warp n-offset (0..96)

    // ldmatrix per-lane row/group selectors
    const int ra  = wm + ((lane & 8) ? 8 : 0) + lane7;     // A row (per mi +16)
    const int gsa = (lane >> 4) & 1;                       // A kgroup select
    const int rb  = wn + ((lane & 16) ? 8 : 0) + lane7;    // B row (per pair +16)
    const int gsb = (lane >> 3) & 1;                       // B kgroup select

    const unsigned int sbase = smem_u32(dyn);

    if (tid < 128) {
        int n = n0 + tid;
        float qx = pos[2 * n], qy = pos[2 * n + 1];
        s_qx[tid] = qx; s_qy[tid] = qy;
        s_sqb[tid] = __fadd_rn(__fmul_rn(qx, qx), __fmul_rn(qy, qy));
    }

    float d[4][4][4];
#pragma unroll
    for (int mi = 0; mi < 4; mi++)
#pragma unroll
        for (int ni = 0; ni < 4; ni++)
#pragma unroll
            for (int r = 0; r < 4; r++) d[mi][ni][r] = 0.0f;

    stage_chunk(sbase, m0, n0, 0, tid);
    CP_COMMIT();

#pragma unroll 1
    for (int ch = 0; ch < 8; ch++) {
        CP_WAIT0();            // current chunk's data landed (this thread)
        __syncthreads();       // all threads landed + prev buffer drained
        if (ch < 7) {          // overlap next stage with current compute
            stage_chunk(sbase + ((ch + 1) & 1) * STAGE, m0, n0, (ch + 1) * 64, tid);
            CP_COMMIT();
        }

        const unsigned int buf = sbase + (ch & 1) * STAGE;
#pragma unroll
        for (int ks = 0; ks < 4; ks++) {
            const unsigned int swa = (unsigned)(((ks * 2 + gsa) ^ lane7) << 4);
            const unsigned int swb = (unsigned)(((ks * 2 + gsb) ^ lane7) << 4);
            unsigned int a[4][4], b[2][4];
#pragma unroll
            for (int mi = 0; mi < 4; mi++) {
                unsigned int ad = buf + (unsigned)((ra + mi * 16) * 128) + swa;
                LDSM_X4(a[mi], ad);
            }
#pragma unroll
            for (int p = 0; p < 2; p++) {
                unsigned int bd = buf + (unsigned)(16384 +
                                    (rb + p * 16) * 128) + swb;
                LDSM_X4(b[p], bd);
            }
#pragma unroll
            for (int mi = 0; mi < 4; mi++)
#pragma unroll
                for (int ni = 0; ni < 4; ni++) {
                    const int p = ni >> 1, o = (ni & 1) * 2;
                    MMA16816(d[mi][ni], a[mi], b[p][o], b[p][o + 1]);
                }
        }
    }
    __syncthreads();   // all warps done with LDSM before smem_t overlay

    // ---- epilogue in registers -> padded smem (exact validated fp ops) ----
    float* smem_t = (float*)dyn;   // 128 x 129 floats (staging done)
    const float lam = g_lam, oml = g_one_m_lam, temp = g_temp;
#pragma unroll
    for (int mi = 0; mi < 4; mi++) {
#pragma unroll
        for (int rh = 0; rh < 2; rh++) {
            int lr = wm + mi * 16 + gid + rh * 8;
            int m = m0 + lr;
            float px = pos[2 * m], py = pos[2 * m + 1];
            float sqa = __fadd_rn(__fmul_rn(px, px), __fmul_rn(py, py));
#pragma unroll
            for (int ni = 0; ni < 4; ni++) {
#pragma unroll
                for (int cc = 0; cc < 2; cc++) {
                    int lc = wn + ni * 8 + 2 * tig + cc;
                    float sim = d[mi][ni][rh * 2 + cc];
                    float qx = s_qx[lc], qy = s_qy[lc];
                    float P = __fmaf_rn(py, qy, __fmul_rn(px, qx));
                    float S = __fadd_rn(sqa, s_sqb[lc]);
                    float d2 = __fadd_rn(S, -(2.0f * P));
                    d2 = fmaxf(d2, 0.0f);
                    float sp = expf(-__fdiv_rn(d2, 5000.0f));
                    float comb = __fadd_rn(__fmul_rn(lam, sim),
                                           __fmul_rn(oml, sp));
                    smem_t[lr * 129 + lc] = sigmoid_f(__fmul_rn(comb, temp));
                }
            }
        }
    }
    __syncthreads();

    // ---- stores: normal rows + mirrored rows (conflict-free, stride 129) ----
    const bool diag = (bi == bj);
#pragma unroll 1
    for (int rr = 0; rr < 16; rr++) {
        int r = wid * 16 + rr;
        float* orow = outp + (size_t)(m0 + r) * NN + n0;
#pragma unroll
        for (int c = lane; c < 128; c += 32)
            orow[c] = smem_t[r * 129 + c];
        if (!diag) {
            float* mrow = outp + (size_t)(n0 + r) * NN + m0;
#pragma unroll
            for (int c2 = lane; c2 < 128; c2 += 32)
                mrow[c2] = smem_t[c2 * 129 + r];
        }
    }
}

// ---------------------------------------------------------------------------
// Kernel 3: per-row exact top-k, single-histogram selection.
// adj in (0.34,0.74) -> one 2048-bin histogram (bits>=14 over [0.125,2))
// localizes the k-th value; collect bins >= B-2 (superset of all elements
// >= band_lo since bin width >= 2*TAU+slack), exact parallel rank gives the
// SAME Tf / n_above / band membership as the old 4-pass radix. Refinement
// (warp-per-candidate ref-replica keys) and write semantics unchanged.
// NOTE: static smem ~18 KB + 32 KB dynamic > 48 KB default -> needs the
// MaxDynamicSharedMemorySize opt-in on this kernel too (round-16 failure).
// ---------------------------------------------------------------------------
#define TAU 1.5e-4f
#define MAXBAND 128
#define KT 512
#define CAP 1024
#define HBINS 2048
#define HBASE 0x3E000000u
#define HSHIFT 14

__device__ __forceinline__ int hbin_of(unsigned int v) {
    int b = ((int)(v - HBASE)) >> HSHIFT;   // arithmetic shift; negative if v<base
    return min(max(b, 0), HBINS - 1);
}

__global__ void topk_kernel(float* __restrict__ out,
                            const int* __restrict__ kptr,
                            long long out_size) {
    const int row = blockIdx.x;
    const int tid = threadIdx.x;
    const int lane = tid & 31;
    const int wid = tid >> 5;

    __shared__ int hist[HBINS];
    __shared__ int wsum[64];
    __shared__ int sh_binB;
    __shared__ int sh_cnt, sh_nabove, sh_bandcnt;
    __shared__ float sh_Tf;
    __shared__ float cand_v[CAP];
    __shared__ int cand_i[CAP];
    __shared__ int bandidx[MAXBAND];
    __shared__ unsigned int bandkey[MAXBAND];
    __shared__ unsigned char bandkeep[MAXBAND];
    extern __shared__ unsigned int srow[];   // NN uint32

    const int k = *kptr;
    const unsigned int* arow = (const unsigned int*)(out + (size_t)row * NN);

    for (int i = tid; i < HBINS; i += KT) hist[i] = 0;
    if (tid == 0) { sh_cnt = 0; sh_nabove = 0; sh_bandcnt = 0; }
    __syncthreads();

    // scan 1: load row + histogram (warp-aggregated atomics)
    for (int j = tid; j < NN; j += KT) {
        unsigned int v = arow[j];
        srow[j] = v;
        int bin = hbin_of(v);
        unsigned int peers = __match_any_sync(0xFFFFFFFFu, bin);
        int leader = __ffs(peers) - 1;
        if (lane == leader) atomicAdd(&hist[bin], __popc(peers));
    }
    __syncthreads();

    // find bin B containing the k-th largest (suffix walk, two-level)
    if (tid < 64) {
        int s = 0;
        for (int b2 = 0; b2 < 32; b2++) s += hist[tid * 32 + b2];
        wsum[tid] = s;
    }
    __syncthreads();
    if (tid == 0) {
        int rem = k;
        int w = 63;
        for (; w > 0; w--) {
            if (rem - wsum[w] <= 0) break;
            rem -= wsum[w];
        }
        int b = w * 32 + 31;
        for (; b > w * 32; b--) {
            if (rem - hist[b] <= 0) break;
            rem -= hist[b];
        }
        sh_binB = b;
    }
    __syncthreads();
    const int B = sh_binB;

    // scan 2: collect candidates in bins >= B-2 (retry with >= B on overflow)
    int Blo = (B >= 2) ? B - 2 : 0;
    for (int attempt = 0; attempt < 2; attempt++) {
        for (int j = tid; j < NN; j += KT) {
            unsigned int v = srow[j];
            if (hbin_of(v) >= Blo) {
                int p = atomicAdd(&sh_cnt, 1);
                if (p < CAP) { cand_v[p] = __uint_as_float(v); cand_i[p] = j; }
            }
        }
        __syncthreads();
        if (sh_cnt <= CAP) break;
        // overflow (astronomically unlikely): retry with tighter range
        __syncthreads();
        if (tid == 0) sh_cnt = 0;
        Blo = B;
        __syncthreads();
    }
    const int C = min(sh_cnt, CAP);

    // exact k-th largest among candidates (parallel rank; ties well-defined)
    for (int i = tid; i < C; i += KT) {
        float vi = cand_v[i];
        int rs = 0, eq = 0;
        for (int j2 = 0; j2 < C; j2++) {
            float vj = cand_v[j2];
            rs += (vj > vi);
            eq += (vj == vi);
        }
        if (rs < k && k <= rs + eq) sh_Tf = vi;
    }
    __syncthreads();
    const float Tf = sh_Tf;
    const float band_hi = Tf + TAU;
    const float band_lo = Tf - TAU;

    // n_above + band membership (all such elements are collected)
    for (int i = tid; i < C; i += KT) {
        float v = cand_v[i];
        if (v > band_hi) {
            atomicAdd(&sh_nabove, 1);
        } else if (v >= band_lo) {
            int p = atomicAdd(&sh_bandcnt, 1);
            if (p < MAXBAND) bandidx[p] = cand_i[i];
        }
    }
    __syncthreads();

    const int n_above = sh_nabove;
    const int band_cnt_raw = sh_bandcnt;
    const int band_cnt = min(band_cnt_raw, MAXBAND);
    const int need = k - n_above;     // >= 1 always

    bool refined = false;
    if (band_cnt_raw <= MAXBAND && band_cnt_raw > need) {
        refined = true;
        const float lamk = g_lam_key, omlk = g_oml_key, temp = g_temp;
        const float* fa = &g_featn[(size_t)row * DD];

        // warp-per-candidate refinement (lane-strided fp64 dot + shuffles)
        for (int c = wid; c < band_cnt; c += 16) {
            int j = bandidx[c];
            const float* fb = &g_featn[(size_t)j * DD];
            double part = 0.0;
#pragma unroll
            for (int t2 = lane; t2 < DD; t2 += 32)
                part += (double)fa[t2] * (double)fb[t2];
#pragma unroll
            for (int off = 16; off > 0; off >>= 1)
                part += __shfl_down_sync(0xFFFFFFFFu, part, off);
            if (lane == 0) {
                float simf = (float)part;       // correctly-rounded fp32 sim
                float a = ref_adj_key(simf, row, j, lamk, omlk, temp);
                bandkey[c] = __float_as_uint(a);
                bandkeep[c] = 0;
            }
        }
        __syncthreads();

        if (tid == 0) {
            for (int pick = 0; pick < need; pick++) {
                int best = -1;
                for (int c = 0; c < band_cnt; c++) {
                    if (bandkeep[c]) continue;
                    if (best < 0 ||
                        bandkey[c] > bandkey[best] ||
                        (bandkey[c] == bandkey[best] && bandidx[c] < bandidx[best]))
                        best = c;
                }
                bandkeep[best] = 1;
            }
        }
        __syncthreads();
    }

    // scan 3: write masked output (in place)
    float* orow = out + (size_t)row * NN;
    for (int j = tid; j < NN; j += KT) {
        float v = __uint_as_float(srow[j]);
        float o = 0.0f;
        if (v > band_hi) {
            o = v;
        } else if (v >= band_lo) {
            if (!refined) {
                if (band_cnt_raw <= MAXBAND) {
                    o = v;                       // band_cnt == need: keep all
                } else {
                    o = (v >= Tf) ? v : 0.0f;    // overflow fallback
                }
            } else {
                for (int c = 0; c < band_cnt; c++) {
                    if (bandidx[c] == j) { o = bandkeep[c] ? v : 0.0f; break; }
                }
            }
        }
        orow[j] = o;
    }

    if (row == 0 && tid == 0 && out_size > (long long)NN * NN)
        out[(size_t)NN * NN] = g_lam;    // second tuple output: lam scalar
}

// ---------------------------------------------------------------------------
extern "C" void kernel_launch(void* const* d_in, const int* in_sizes, int n_in,
                              void* d_out, int out_size) {
    const float* feat = (const float*)d_in[0];   // (8192, 512)
    const float* pos  = (const float*)d_in[1];   // (8192, 2)
    const float* lamw = (const float*)d_in[2];   // scalar
    const float* temp = (const float*)d_in[3];   // scalar
    const int*   kptr = (const int*)d_in[4];     // scalar int
    float* out = (float*)d_out;

    cudaFuncSetAttribute(adj_gemm_mma,
                         cudaFuncAttributeMaxDynamicSharedMemorySize, DYN_SMEM);
    // topk: ~18 KB static + 32 KB dynamic exceeds the 48 KB default cap;
    // opt in so the dynamic portion is granted alongside the static usage.
    cudaFuncSetAttribute(topk_kernel,
                         cudaFuncAttributeMaxDynamicSharedMemorySize,
                         NN * (int)sizeof(unsigned int));

    prep_kernel<<<NN / 8, 256>>>(feat, pos, lamw, temp);
    adj_gemm_mma<<<NPAIRS, GT, DYN_SMEM>>>(pos, out);
    topk_kernel<<<NN, KT, NN * sizeof(unsigned int)>>>(out, kptr,
                                                       (long long)out_size);
}